// round 5
// baseline (speedup 1.0000x reference)
#include <cuda_runtime.h>

#define BB 2
#define CC 64
#define HH 192
#define WW 192
#define HWX (HH*WW)
#define KK 7

// q,k scratch in quad-channel layout: [b][c/4][hw] as float4 (channels c..c+3)
__device__ float4 d_q4[BB*16*HWX];
__device__ float4 d_k4[BB*16*HWX];

__device__ __forceinline__ void ffma2(unsigned long long &acc,
                                      unsigned long long a,
                                      unsigned long long b) {
    asm("fma.rn.f32x2 %0, %1, %2, %0;" : "+l"(acc) : "l"(a), "l"(b));
}
__device__ __forceinline__ float f2lo(unsigned long long v) {
    return __uint_as_float((unsigned)(v & 0xffffffffu));
}
__device__ __forceinline__ float f2hi(unsigned long long v) {
    return __uint_as_float((unsigned)(v >> 32));
}

// ---------------------------------------------------------------------------
// Kernel 1: LN + [128x65] matvec, register-blocked, f32x2 FMA. (unchanged)
// ---------------------------------------------------------------------------
#define K1_PIX 64
#define K1_NT 256
#define WSTRIDE 132
#define K1_SMEM (65*K1_PIX*8 + 65*WSTRIDE*4)

__global__ void __launch_bounds__(K1_NT)
mspn_k1(const float* __restrict__ g, const float* __restrict__ cd,
        const float* __restrict__ mask, const float* __restrict__ lnw,
        const float* __restrict__ lnb, const float* __restrict__ convw,
        const float* __restrict__ convb)
{
    extern __shared__ __align__(16) char dsm[];
    float2* zsh = (float2*)dsm;                       // [65][64]
    float*  wsh = (float*)(dsm + 65*K1_PIX*8);        // [65][WSTRIDE]
    __shared__ float mu_sh[K1_PIX], ri_sh[K1_PIX], mk_sh[K1_PIX];
    __shared__ float bsh[128];

    const int t = threadIdx.x;
    const int p0 = blockIdx.x * K1_PIX;
    const int b = p0 / HWX;
    const int hw0 = p0 - b*HWX;

    for (int i = t; i < 128*65; i += K1_NT) {
        int oc = i / 65, c = i - oc*65;
        wsh[c*WSTRIDE + oc] = convw[i];
    }
    for (int i = t; i < 64*K1_PIX; i += K1_NT) {
        int c = i >> 6, px = i & 63;
        zsh[c*K1_PIX + px].x = g[(b*CC + c)*HWX + hw0 + px];
    }
    if (t < K1_PIX) {
        float cv = cd[p0 + t];
        zsh[64*K1_PIX + t] = make_float2(cv, cv);
        mk_sh[t] = mask[p0 + t];
    }
    if (t >= 128 && t < 256) bsh[t-128] = convb[t-128];
    __syncthreads();

    if (t < K1_PIX) {
        float s = 0.f;
        #pragma unroll
        for (int c = 0; c < 64; c++) s += zsh[c*K1_PIX + t].x;
        float mu = s * (1.f/64.f);
        float v = 0.f;
        #pragma unroll
        for (int c = 0; c < 64; c++) { float d = zsh[c*K1_PIX + t].x - mu; v += d*d; }
        mu_sh[t] = mu;
        ri_sh[t] = rsqrtf(v * (1.f/64.f) + 1e-6f);
    }
    __syncthreads();

    for (int i = t; i < 64*K1_PIX; i += K1_NT) {
        int c = i >> 6, px = i & 63;
        float v = (zsh[c*K1_PIX + px].x - mu_sh[px]) * ri_sh[px] * lnw[c] + lnb[c];
        zsh[c*K1_PIX + px] = make_float2(v, v);
    }
    __syncthreads();

    const int lane = t & 31, wid = t >> 5;
    const int oc0 = wid * 16;

    unsigned long long acc[16];
    #pragma unroll
    for (int i = 0; i < 16; i++) acc[i] = 0ULL;

    #pragma unroll 13
    for (int c = 0; c < 65; c++) {
        unsigned long long z0 = *(const unsigned long long*)&zsh[c*K1_PIX + lane];
        unsigned long long z1 = *(const unsigned long long*)&zsh[c*K1_PIX + lane + 32];
        const float* wr = &wsh[c*WSTRIDE + oc0];
        ulonglong2 wa = *(const ulonglong2*)(wr);
        ulonglong2 wb = *(const ulonglong2*)(wr + 4);
        ulonglong2 wc = *(const ulonglong2*)(wr + 8);
        ulonglong2 wd = *(const ulonglong2*)(wr + 12);
        ffma2(acc[0], z0, wa.x); ffma2(acc[1], z0, wa.y);
        ffma2(acc[2], z0, wb.x); ffma2(acc[3], z0, wb.y);
        ffma2(acc[4], z0, wc.x); ffma2(acc[5], z0, wc.y);
        ffma2(acc[6], z0, wd.x); ffma2(acc[7], z0, wd.y);
        ffma2(acc[8],  z1, wa.x); ffma2(acc[9],  z1, wa.y);
        ffma2(acc[10], z1, wb.x); ffma2(acc[11], z1, wb.y);
        ffma2(acc[12], z1, wc.x); ffma2(acc[13], z1, wc.y);
        ffma2(acc[14], z1, wd.x); ffma2(acc[15], z1, wd.y);
    }

    const bool isk = (oc0 >= 64);
    const int cq0 = (isk ? oc0 - 64 : oc0) >> 2;
    float4* dst = isk ? d_k4 : d_q4;
    float bias[16];
    #pragma unroll
    for (int i = 0; i < 16; i++) bias[i] = bsh[oc0 + i];

    #pragma unroll
    for (int px = 0; px < 2; px++) {
        const int pl = lane + px*32;
        const int pix = hw0 + pl;
        const float m = mk_sh[pl];
        float vals[16];
        #pragma unroll
        for (int j = 0; j < 8; j++) {
            unsigned long long a = acc[px*8 + j];
            vals[2*j]   = f2lo(a) + bias[2*j];
            vals[2*j+1] = f2hi(a) + bias[2*j+1];
        }
        if (isk) {
            #pragma unroll
            for (int i = 0; i < 16; i++) vals[i] *= m;
        }
        #pragma unroll
        for (int q = 0; q < 4; q++) {
            float4 o = make_float4(vals[4*q], vals[4*q+1], vals[4*q+2], vals[4*q+3]);
            dst[(b*16 + cq0 + q)*HWX + pix] = o;
        }
    }
}

// ---------------------------------------------------------------------------
// Kernel 2: 7x7 clamped-window attention, lane-pair channel split.
// Tile 32x4 px, 256 threads: lane pair (2p, 2p+1) shares pixel p of the
// half-row; even lane accumulates quads 0-7 (ch 0-31), odd lane quads 8-15.
// 49 logits merged by shfl.xor(1). Double-buffered k staging (2 quads/round).
// ---------------------------------------------------------------------------
#define TX 32
#define TY4 4
#define K2_NT 256
#define HR 10          // TY4 + 6
#define HC 38          // TX + 6
#define HSZ (HR*HC)

__global__ void __launch_bounds__(K2_NT, 3)
mspn_k2(const float* __restrict__ cd, const float* __restrict__ sd,
        const float* __restrict__ mask, const float* __restrict__ rpb,
        float* __restrict__ out)
{
    __shared__ float4 ksh[2][2][HSZ];     // [buf][chalf][halo]
    __shared__ float cdsh[HSZ];
    __shared__ float msh[HSZ];
    __shared__ float rpbsh[169];

    const int t = threadIdx.x;
    const int b  = blockIdx.z;
    const int h0 = blockIdx.y * TY4;
    const int w0 = blockIdx.x * TX;
    const int r_off = h0 - 3, c_off = w0 - 3;

    // prologue: cd/mask halo + rpb
    for (int i = t; i < HSZ; i += K2_NT) {
        int rr = i / HC, cc = i - rr*HC;
        int r = r_off + rr, col = c_off + cc;
        float cv = 0.f, mv = 0.f;
        if (r >= 0 && r < HH && col >= 0 && col < WW) {
            int idx = b*HWX + r*WW + col;
            cv = cd[idx]; mv = mask[idx];
        }
        cdsh[i] = cv; msh[i] = mv;
    }
    if (t < 169) rpbsh[t] = rpb[t];

    const int lane = t & 31, wid = t >> 5;
    const int chalf = lane & 1;                 // 0: ch 0-31, 1: ch 32-63
    const int pxi = lane >> 1;                  // 0..15 within half-row
    const int row = wid >> 1;                   // 0..3
    const int h = h0 + row;
    const int w = w0 + (wid & 1)*16 + pxi;
    int rs = h - 3; if (rs < 0) rs = 0; if (rs > HH-KK) rs = HH-KK;
    int cs = w - 3; if (cs < 0) cs = 0; if (cs > WW-KK) cs = WW-KK;
    const int ri0 = rs - r_off;                 // 0..3
    const int ci0 = cs - c_off;

    float attn[49];
    #pragma unroll
    for (int i = 0; i < 49; i++) attn[i] = 0.f;

    const int qpix = h*WW + w;
    const int qbase = (b*16 + chalf*8)*HWX + qpix;

    // stage round 0 (quads 0 and 8) into buffer 0
    #pragma unroll
    for (int half = 0; half < 2; half++) {
        const float4* src = &d_k4[(b*16 + half*8)*HWX];
        for (int i = t; i < HSZ; i += K2_NT) {
            int rr = i / HC, cc = i - rr*HC;
            int r = r_off + rr, col = c_off + cc;
            float4 v = make_float4(0.f,0.f,0.f,0.f);
            if (r >= 0 && r < HH && col >= 0 && col < WW) v = src[r*WW + col];
            ksh[0][half][i] = v;
        }
    }

    for (int cq = 0; cq < 8; cq++) {
        __syncthreads();
        if (cq < 7) {
            const int buf = (cq + 1) & 1;
            #pragma unroll
            for (int half = 0; half < 2; half++) {
                const float4* src = &d_k4[(b*16 + half*8 + cq + 1)*HWX];
                for (int i = t; i < HSZ; i += K2_NT) {
                    int rr = i / HC, cc = i - rr*HC;
                    int r = r_off + rr, col = c_off + cc;
                    float4 v = make_float4(0.f,0.f,0.f,0.f);
                    if (r >= 0 && r < HH && col >= 0 && col < WW) v = src[r*WW + col];
                    ksh[buf][half][i] = v;
                }
            }
        }
        const float4 q4 = d_q4[qbase + cq*HWX];
        const float4* kb = &ksh[cq & 1][chalf][ri0*HC + ci0];

        #pragma unroll
        for (int i = 0; i < KK; i++) {
            #pragma unroll
            for (int j = 0; j < KK; j++) {
                float4 k4 = kb[i*HC + j];
                attn[i*KK+j] += q4.x*k4.x + q4.y*k4.y + q4.z*k4.z + q4.w*k4.w;
            }
        }
    }

    // merge channel halves across the lane pair
    #pragma unroll
    for (int i = 0; i < 49; i++)
        attn[i] += __shfl_xor_sync(0xffffffffu, attn[i], 1);

    // epilogue on even lanes only
    if (chalf == 0) {
        const int pbr = 6 - (h - rs);
        const int pbc = 6 - (w - cs);
        float mx = -1e30f;
        #pragma unroll
        for (int i = 0; i < KK; i++)
            #pragma unroll
            for (int j = 0; j < KK; j++) {
                float a = attn[i*KK+j] + rpbsh[(pbr+i)*13 + pbc + j];
                attn[i*KK+j] = a;
                mx = fmaxf(mx, a);
            }
        float ssum = 0.f;
        #pragma unroll
        for (int i = 0; i < 49; i++) { float e = __expf(attn[i]-mx); attn[i]=e; ssum+=e; }
        const float inv = 1.f/ssum;

        float cdo = 0.f, mo = 0.f;
        #pragma unroll
        for (int i = 0; i < KK; i++) {
            const int base = (ri0+i)*HC + ci0;
            #pragma unroll
            for (int j = 0; j < KK; j++) {
                float a = attn[i*KK+j];
                cdo += a * cdsh[base+j];
                mo  += a * msh[base+j];
            }
        }
        cdo *= inv; mo *= inv;

        const int p = b*HWX + h*WW + w;
        const float m = mask[p], cdv = cd[p], sdv = sd[p];
        cdo = cdo*m + cdv*(1.f - m);
        if (sdv > 0.f) { cdo = sdv; mo = m; }
        out[p] = cdo;
        out[BB*HWX + p] = mo;
    }
}

// ---------------------------------------------------------------------------
extern "C" void kernel_launch(void* const* d_in, const int* in_sizes, int n_in,
                              void* d_out, int out_size)
{
    const float* g     = (const float*)d_in[0];
    const float* cd    = (const float*)d_in[1];
    const float* sd    = (const float*)d_in[2];
    const float* mask  = (const float*)d_in[3];
    const float* lnw   = (const float*)d_in[4];
    const float* lnb   = (const float*)d_in[5];
    const float* convw = (const float*)d_in[6];
    const float* convb = (const float*)d_in[7];
    const float* rpb   = (const float*)d_in[8];
    float* out = (float*)d_out;

    cudaFuncSetAttribute(mspn_k1, cudaFuncAttributeMaxDynamicSharedMemorySize, K1_SMEM);
    mspn_k1<<<(BB*HWX)/K1_PIX, K1_NT, K1_SMEM>>>(g, cd, mask, lnw, lnb, convw, convb);

    dim3 grid2(WW/TX, HH/TY4, BB);
    mspn_k2<<<grid2, K2_NT>>>(cd, sd, mask, rpb, out);
}

// round 6
// speedup vs baseline: 1.1079x; 1.1079x over previous
#include <cuda_runtime.h>

#define BB 2
#define CC 64
#define HH 192
#define WW 192
#define HWX (HH*WW)
#define KK 7

// q,k scratch in quad-channel layout: [b][c/4][hw] as float4 (channels c..c+3)
__device__ float4 d_q4[BB*16*HWX];
__device__ float4 d_k4[BB*16*HWX];

__device__ __forceinline__ void ffma2(unsigned long long &acc,
                                      unsigned long long a,
                                      unsigned long long b) {
    asm("fma.rn.f32x2 %0, %1, %2, %0;" : "+l"(acc) : "l"(a), "l"(b));
}
__device__ __forceinline__ float f2lo(unsigned long long v) {
    return __uint_as_float((unsigned)(v & 0xffffffffu));
}
__device__ __forceinline__ float f2hi(unsigned long long v) {
    return __uint_as_float((unsigned)(v >> 32));
}

// ---------------------------------------------------------------------------
// Kernel 1: LN + [128x65] matvec, register-blocked, f32x2 FMA.
// Weight staging iterates oc fastest -> conflict-free STS.
// ---------------------------------------------------------------------------
#define K1_PIX 64
#define K1_NT 256
#define WSTRIDE 132
#define K1_SMEM (65*K1_PIX*8 + 65*WSTRIDE*4)

__global__ void __launch_bounds__(K1_NT)
mspn_k1(const float* __restrict__ g, const float* __restrict__ cd,
        const float* __restrict__ mask, const float* __restrict__ lnw,
        const float* __restrict__ lnb, const float* __restrict__ convw,
        const float* __restrict__ convb)
{
    extern __shared__ __align__(16) char dsm[];
    float2* zsh = (float2*)dsm;                       // [65][64]
    float*  wsh = (float*)(dsm + 65*K1_PIX*8);        // [65][WSTRIDE]
    __shared__ float mu_sh[K1_PIX], ri_sh[K1_PIX], mk_sh[K1_PIX];
    __shared__ float bsh[128];

    const int t = threadIdx.x;
    const int p0 = blockIdx.x * K1_PIX;
    const int b = p0 / HWX;
    const int hw0 = p0 - b*HWX;

    // transpose stage: consecutive lanes -> consecutive oc -> conflict-free STS
    for (int i = t; i < 65*128; i += K1_NT) {
        int c = i >> 7, oc = i & 127;
        wsh[c*WSTRIDE + oc] = convw[oc*65 + c];
    }
    for (int i = t; i < 64*K1_PIX; i += K1_NT) {
        int c = i >> 6, px = i & 63;
        zsh[c*K1_PIX + px].x = g[(b*CC + c)*HWX + hw0 + px];
    }
    if (t < K1_PIX) {
        float cv = cd[p0 + t];
        zsh[64*K1_PIX + t] = make_float2(cv, cv);
        mk_sh[t] = mask[p0 + t];
    }
    if (t >= 128 && t < 256) bsh[t-128] = convb[t-128];
    __syncthreads();

    if (t < K1_PIX) {
        float s = 0.f;
        #pragma unroll
        for (int c = 0; c < 64; c++) s += zsh[c*K1_PIX + t].x;
        float mu = s * (1.f/64.f);
        float v = 0.f;
        #pragma unroll
        for (int c = 0; c < 64; c++) { float d = zsh[c*K1_PIX + t].x - mu; v += d*d; }
        mu_sh[t] = mu;
        ri_sh[t] = rsqrtf(v * (1.f/64.f) + 1e-6f);
    }
    __syncthreads();

    for (int i = t; i < 64*K1_PIX; i += K1_NT) {
        int c = i >> 6, px = i & 63;
        float v = (zsh[c*K1_PIX + px].x - mu_sh[px]) * ri_sh[px] * lnw[c] + lnb[c];
        zsh[c*K1_PIX + px] = make_float2(v, v);
    }
    __syncthreads();

    const int lane = t & 31, wid = t >> 5;
    const int oc0 = wid * 16;

    unsigned long long acc[16];
    #pragma unroll
    for (int i = 0; i < 16; i++) acc[i] = 0ULL;

    #pragma unroll 13
    for (int c = 0; c < 65; c++) {
        unsigned long long z0 = *(const unsigned long long*)&zsh[c*K1_PIX + lane];
        unsigned long long z1 = *(const unsigned long long*)&zsh[c*K1_PIX + lane + 32];
        const float* wr = &wsh[c*WSTRIDE + oc0];
        ulonglong2 wa = *(const ulonglong2*)(wr);
        ulonglong2 wb = *(const ulonglong2*)(wr + 4);
        ulonglong2 wc = *(const ulonglong2*)(wr + 8);
        ulonglong2 wd = *(const ulonglong2*)(wr + 12);
        ffma2(acc[0], z0, wa.x); ffma2(acc[1], z0, wa.y);
        ffma2(acc[2], z0, wb.x); ffma2(acc[3], z0, wb.y);
        ffma2(acc[4], z0, wc.x); ffma2(acc[5], z0, wc.y);
        ffma2(acc[6], z0, wd.x); ffma2(acc[7], z0, wd.y);
        ffma2(acc[8],  z1, wa.x); ffma2(acc[9],  z1, wa.y);
        ffma2(acc[10], z1, wb.x); ffma2(acc[11], z1, wb.y);
        ffma2(acc[12], z1, wc.x); ffma2(acc[13], z1, wc.y);
        ffma2(acc[14], z1, wd.x); ffma2(acc[15], z1, wd.y);
    }

    const bool isk = (oc0 >= 64);
    const int cq0 = (isk ? oc0 - 64 : oc0) >> 2;
    float4* dst = isk ? d_k4 : d_q4;
    float bias[16];
    #pragma unroll
    for (int i = 0; i < 16; i++) bias[i] = bsh[oc0 + i];

    #pragma unroll
    for (int px = 0; px < 2; px++) {
        const int pl = lane + px*32;
        const int pix = hw0 + pl;
        const float m = mk_sh[pl];
        float vals[16];
        #pragma unroll
        for (int j = 0; j < 8; j++) {
            unsigned long long a = acc[px*8 + j];
            vals[2*j]   = f2lo(a) + bias[2*j];
            vals[2*j+1] = f2hi(a) + bias[2*j+1];
        }
        if (isk) {
            #pragma unroll
            for (int i = 0; i < 16; i++) vals[i] *= m;
        }
        #pragma unroll
        for (int q = 0; q < 4; q++) {
            float4 o = make_float4(vals[4*q], vals[4*q+1], vals[4*q+2], vals[4*q+3]);
            dst[(b*16 + cq0 + q)*HWX + pix] = o;
        }
    }
}

// ---------------------------------------------------------------------------
// Kernel 2: 7x7 clamped-window attention, 1 px/thread, TY=8 tile.
// 2 channel-quads per round (8 rounds), double-buffered, q prefetch.
// Clamped windows never touch out-of-image halo -> branch-free clamped staging.
// ---------------------------------------------------------------------------
#define TX 32
#define TY 8
#define K2_NT 256
#define HR 14          // TY + 6
#define HC 38          // TX + 6
#define HSZ (HR*HC)

__device__ __forceinline__ int iclamp(int v, int hi) {
    return v < 0 ? 0 : (v > hi ? hi : v);
}

__global__ void __launch_bounds__(K2_NT, 2)
mspn_k2(const float* __restrict__ cd, const float* __restrict__ sd,
        const float* __restrict__ mask, const float* __restrict__ rpb,
        float* __restrict__ out)
{
    __shared__ float4 ksh[2][2][HSZ];   // [buf][sub][pos]
    __shared__ float cdsh[HSZ];
    __shared__ float msh[HSZ];
    __shared__ float rpbsh[169];

    const int t = threadIdx.x;
    const int b  = blockIdx.z;
    const int h0 = blockIdx.y * TY;
    const int w0 = blockIdx.x * TX;
    const int r_off = h0 - 3, c_off = w0 - 3;

    // cd/mask halo (clamped addressing; OOB positions never read) + rpb
    for (int i = t; i < HSZ; i += K2_NT) {
        int rr = i / HC, cc = i - rr*HC;
        int r = iclamp(r_off + rr, HH-1), col = iclamp(c_off + cc, WW-1);
        int idx = b*HWX + r*WW + col;
        cdsh[i] = cd[idx];
        msh[i]  = mask[idx];
    }
    if (t < 169) rpbsh[t] = rpb[t];

    const int lw = t & 31, lh = t >> 5;
    const int h = h0 + lh, w = w0 + lw;
    int rs = h - 3; if (rs < 0) rs = 0; if (rs > HH-KK) rs = HH-KK;
    int cs = w - 3; if (cs < 0) cs = 0; if (cs > WW-KK) cs = WW-KK;
    const int ri0 = rs - r_off;
    const int ci0 = cs - c_off;

    float attn[49];
    #pragma unroll
    for (int i = 0; i < 49; i++) attn[i] = 0.f;

    const int qpix = h*WW + w;
    const float4* qb = &d_q4[b*16*HWX + qpix];
    const float4* kbase = &d_k4[b*16*HWX];

    // stage round 0 (quads 0,1) into buffer 0
    #pragma unroll
    for (int sub = 0; sub < 2; sub++) {
        const float4* src = kbase + sub*HWX;
        for (int i = t; i < HSZ; i += K2_NT) {
            int rr = i / HC, cc = i - rr*HC;
            int r = iclamp(r_off + rr, HH-1), col = iclamp(c_off + cc, WW-1);
            ksh[0][sub][i] = src[r*WW + col];
        }
    }
    float4 qa = qb[0], qc = qb[HWX];     // round-0 q pair

    for (int rd = 0; rd < 8; rd++) {
        __syncthreads();
        if (rd < 7) {
            const int buf = (rd + 1) & 1;
            #pragma unroll
            for (int sub = 0; sub < 2; sub++) {
                const float4* src = kbase + (2*rd + 2 + sub)*HWX;
                for (int i = t; i < HSZ; i += K2_NT) {
                    int rr = i / HC, cc = i - rr*HC;
                    int r = iclamp(r_off + rr, HH-1), col = iclamp(c_off + cc, WW-1);
                    ksh[buf][sub][i] = src[r*WW + col];
                }
            }
        }
        const float4 q0 = qa, q1 = qc;
        if (rd < 7) {                     // prefetch next round's q
            qa = qb[(2*rd + 2)*HWX];
            qc = qb[(2*rd + 3)*HWX];
        }
        const float4* k0 = &ksh[rd & 1][0][ri0*HC + ci0];
        const float4* k1 = &ksh[rd & 1][1][ri0*HC + ci0];

        #pragma unroll
        for (int i = 0; i < KK; i++) {
            #pragma unroll
            for (int j = 0; j < KK; j++) {
                float4 ka = k0[i*HC + j];
                float4 kb = k1[i*HC + j];
                float s = attn[i*KK+j];
                s += q0.x*ka.x + q0.y*ka.y + q0.z*ka.z + q0.w*ka.w;
                s += q1.x*kb.x + q1.y*kb.y + q1.z*kb.z + q1.w*kb.w;
                attn[i*KK+j] = s;
            }
        }
    }

    // bias + softmax
    const int pbr = 6 - (h - rs);
    const int pbc = 6 - (w - cs);
    float mx = -1e30f;
    #pragma unroll
    for (int i = 0; i < KK; i++)
        #pragma unroll
        for (int j = 0; j < KK; j++) {
            float a = attn[i*KK+j] + rpbsh[(pbr+i)*13 + pbc + j];
            attn[i*KK+j] = a;
            mx = fmaxf(mx, a);
        }
    float ssum = 0.f;
    #pragma unroll
    for (int i = 0; i < 49; i++) { float e = __expf(attn[i]-mx); attn[i]=e; ssum+=e; }
    const float inv = 1.f/ssum;

    float cdo = 0.f, mo = 0.f;
    #pragma unroll
    for (int i = 0; i < KK; i++) {
        const int base = (ri0+i)*HC + ci0;
        #pragma unroll
        for (int j = 0; j < KK; j++) {
            float a = attn[i*KK+j];
            cdo += a * cdsh[base+j];
            mo  += a * msh[base+j];
        }
    }
    cdo *= inv; mo *= inv;

    const int p = b*HWX + h*WW + w;
    const float m = mask[p], cdv = cd[p], sdv = sd[p];
    cdo = cdo*m + cdv*(1.f - m);
    if (sdv > 0.f) { cdo = sdv; mo = m; }
    out[p] = cdo;
    out[BB*HWX + p] = mo;
}

// ---------------------------------------------------------------------------
extern "C" void kernel_launch(void* const* d_in, const int* in_sizes, int n_in,
                              void* d_out, int out_size)
{
    const float* g     = (const float*)d_in[0];
    const float* cd    = (const float*)d_in[1];
    const float* sd    = (const float*)d_in[2];
    const float* mask  = (const float*)d_in[3];
    const float* lnw   = (const float*)d_in[4];
    const float* lnb   = (const float*)d_in[5];
    const float* convw = (const float*)d_in[6];
    const float* convb = (const float*)d_in[7];
    const float* rpb   = (const float*)d_in[8];
    float* out = (float*)d_out;

    cudaFuncSetAttribute(mspn_k1, cudaFuncAttributeMaxDynamicSharedMemorySize, K1_SMEM);
    mspn_k1<<<(BB*HWX)/K1_PIX, K1_NT, K1_SMEM>>>(g, cd, mask, lnw, lnb, convw, convb);

    dim3 grid2(WW/TX, HH/TY, BB);
    mspn_k2<<<grid2, K2_NT>>>(cd, sd, mask, rpb, out);
}

// round 7
// speedup vs baseline: 1.6592x; 1.4976x over previous
#include <cuda_runtime.h>

#define BB 2
#define CC 64
#define HH 192
#define WW 192
#define HWX (HH*WW)
#define KK 7

// q,k scratch in quad-channel layout: [b][c/4][hw] as float4 (channels c..c+3)
__device__ float4 d_q4[BB*16*HWX];
__device__ float4 d_k4[BB*16*HWX];
// pre-transposed conv weights: wT[c][oc], c in [0,65), oc in [0,128)
__device__ float d_wT[65*128];

__device__ __forceinline__ void ffma2(unsigned long long &acc,
                                      unsigned long long a,
                                      unsigned long long b) {
    asm("fma.rn.f32x2 %0, %1, %2, %0;" : "+l"(acc) : "l"(a), "l"(b));
}
__device__ __forceinline__ float f2lo(unsigned long long v) {
    return __uint_as_float((unsigned)(v & 0xffffffffu));
}
__device__ __forceinline__ float f2hi(unsigned long long v) {
    return __uint_as_float((unsigned)(v >> 32));
}

// ---------------------------------------------------------------------------
// Kernel 0: one-off weight transpose [128][65] -> [65][128].
// ---------------------------------------------------------------------------
__global__ void mspn_k0(const float* __restrict__ convw)
{
    int t = blockIdx.x * 256 + threadIdx.x;
    if (t < 65*128) {
        int oc = t / 65, c = t - oc*65;   // coalesced read of convw[t]
        d_wT[c*128 + oc] = convw[t];
    }
}

// ---------------------------------------------------------------------------
// Kernel 1: LN + [128x65] matvec, register-blocked, f32x2 FMA.
// Weights staged from pre-transposed d_wT: coalesced LDG + conflict-free STS.
// ---------------------------------------------------------------------------
#define K1_PIX 64
#define K1_NT 256
#define WSTRIDE 132
#define K1_SMEM (65*K1_PIX*8 + 65*WSTRIDE*4)

__global__ void __launch_bounds__(K1_NT)
mspn_k1(const float* __restrict__ g, const float* __restrict__ cd,
        const float* __restrict__ mask, const float* __restrict__ lnw,
        const float* __restrict__ lnb, const float* __restrict__ convb)
{
    extern __shared__ __align__(16) char dsm[];
    float2* zsh = (float2*)dsm;                       // [65][64]
    float*  wsh = (float*)(dsm + 65*K1_PIX*8);        // [65][WSTRIDE]
    __shared__ float mu_sh[K1_PIX], ri_sh[K1_PIX], mk_sh[K1_PIX];
    __shared__ float bsh[128];

    const int t = threadIdx.x;
    const int p0 = blockIdx.x * K1_PIX;
    const int b = p0 / HWX;
    const int hw0 = p0 - b*HWX;

    // stage pre-transposed weights: LDG coalesced, STS lane-stride 4B
    for (int i = t; i < 65*128; i += K1_NT) {
        int c = i >> 7, oc = i & 127;
        wsh[c*WSTRIDE + oc] = d_wT[i];
    }
    for (int i = t; i < 64*K1_PIX; i += K1_NT) {
        int c = i >> 6, px = i & 63;
        zsh[c*K1_PIX + px].x = g[(b*CC + c)*HWX + hw0 + px];
    }
    if (t < K1_PIX) {
        float cv = cd[p0 + t];
        zsh[64*K1_PIX + t] = make_float2(cv, cv);
        mk_sh[t] = mask[p0 + t];
    }
    if (t >= 128 && t < 256) bsh[t-128] = convb[t-128];
    __syncthreads();

    if (t < K1_PIX) {
        float s = 0.f;
        #pragma unroll
        for (int c = 0; c < 64; c++) s += zsh[c*K1_PIX + t].x;
        float mu = s * (1.f/64.f);
        float v = 0.f;
        #pragma unroll
        for (int c = 0; c < 64; c++) { float d = zsh[c*K1_PIX + t].x - mu; v += d*d; }
        mu_sh[t] = mu;
        ri_sh[t] = rsqrtf(v * (1.f/64.f) + 1e-6f);
    }
    __syncthreads();

    for (int i = t; i < 64*K1_PIX; i += K1_NT) {
        int c = i >> 6, px = i & 63;
        float v = (zsh[c*K1_PIX + px].x - mu_sh[px]) * ri_sh[px] * lnw[c] + lnb[c];
        zsh[c*K1_PIX + px] = make_float2(v, v);
    }
    __syncthreads();

    const int lane = t & 31, wid = t >> 5;
    const int oc0 = wid * 16;

    unsigned long long acc[16];
    #pragma unroll
    for (int i = 0; i < 16; i++) acc[i] = 0ULL;

    #pragma unroll 13
    for (int c = 0; c < 65; c++) {
        unsigned long long z0 = *(const unsigned long long*)&zsh[c*K1_PIX + lane];
        unsigned long long z1 = *(const unsigned long long*)&zsh[c*K1_PIX + lane + 32];
        const float* wr = &wsh[c*WSTRIDE + oc0];
        ulonglong2 wa = *(const ulonglong2*)(wr);
        ulonglong2 wb = *(const ulonglong2*)(wr + 4);
        ulonglong2 wc = *(const ulonglong2*)(wr + 8);
        ulonglong2 wd = *(const ulonglong2*)(wr + 12);
        ffma2(acc[0], z0, wa.x); ffma2(acc[1], z0, wa.y);
        ffma2(acc[2], z0, wb.x); ffma2(acc[3], z0, wb.y);
        ffma2(acc[4], z0, wc.x); ffma2(acc[5], z0, wc.y);
        ffma2(acc[6], z0, wd.x); ffma2(acc[7], z0, wd.y);
        ffma2(acc[8],  z1, wa.x); ffma2(acc[9],  z1, wa.y);
        ffma2(acc[10], z1, wb.x); ffma2(acc[11], z1, wb.y);
        ffma2(acc[12], z1, wc.x); ffma2(acc[13], z1, wc.y);
        ffma2(acc[14], z1, wd.x); ffma2(acc[15], z1, wd.y);
    }

    const bool isk = (oc0 >= 64);
    const int cq0 = (isk ? oc0 - 64 : oc0) >> 2;
    float4* dst = isk ? d_k4 : d_q4;
    float bias[16];
    #pragma unroll
    for (int i = 0; i < 16; i++) bias[i] = bsh[oc0 + i];

    #pragma unroll
    for (int px = 0; px < 2; px++) {
        const int pl = lane + px*32;
        const int pix = hw0 + pl;
        const float m = mk_sh[pl];
        float vals[16];
        #pragma unroll
        for (int j = 0; j < 8; j++) {
            unsigned long long a = acc[px*8 + j];
            vals[2*j]   = f2lo(a) + bias[2*j];
            vals[2*j+1] = f2hi(a) + bias[2*j+1];
        }
        if (isk) {
            #pragma unroll
            for (int i = 0; i < 16; i++) vals[i] *= m;
        }
        #pragma unroll
        for (int q = 0; q < 4; q++) {
            float4 o = make_float4(vals[4*q], vals[4*q+1], vals[4*q+2], vals[4*q+3]);
            dst[(b*16 + cq0 + q)*HWX + pix] = o;
        }
    }
}

// ---------------------------------------------------------------------------
// Kernel 2: 7x7 clamped-window attention, float4 (4-channel) vectorized.
// (exact R2 version — best measured: 58.9 us)
// ---------------------------------------------------------------------------
#define TX 32
#define TY 8
#define K2_NT 256
#define HR 14
#define HC 38

__global__ void __launch_bounds__(K2_NT)
mspn_k2(const float* __restrict__ cd, const float* __restrict__ sd,
        const float* __restrict__ mask, const float* __restrict__ rpb,
        float* __restrict__ out)
{
    __shared__ float4 ksh[2][HR*HC];
    __shared__ float4 qsh[2][TY*TX];
    __shared__ float cdsh[HR*HC];
    __shared__ float msh[HR*HC];
    __shared__ float rpbsh[169];

    const int t = threadIdx.x;
    const int b  = blockIdx.z;
    const int h0 = blockIdx.y * TY;
    const int w0 = blockIdx.x * TX;
    const int r_off = h0 - 3, c_off = w0 - 3;

    for (int i = t; i < HR*HC; i += K2_NT) {
        int rr = i / HC, cc = i - rr*HC;
        int r = r_off + rr, col = c_off + cc;
        float cv = 0.f, mv = 0.f;
        if (r >= 0 && r < HH && col >= 0 && col < WW) {
            int idx = b*HWX + r*WW + col;
            cv = cd[idx]; mv = mask[idx];
        }
        cdsh[i] = cv; msh[i] = mv;
    }
    if (t < 169) rpbsh[t] = rpb[t];

    const int lw = t & 31, lh = t >> 5;
    const int h = h0 + lh, w = w0 + lw;
    int rs = h - 3; if (rs < 0) rs = 0; if (rs > HH-KK) rs = HH-KK;
    int cs = w - 3; if (cs < 0) cs = 0; if (cs > WW-KK) cs = WW-KK;
    const int ri0 = rs - r_off;
    const int ci0 = cs - c_off;

    float attn[49];
    #pragma unroll
    for (int i = 0; i < 49; i++) attn[i] = 0.f;

    const int qpix = (h0 + lh)*WW + w0 + lw;

    for (int cq = 0; cq < 16; cq += 2) {
        __syncthreads();   // also orders cdsh/rpbsh before post-loop reads
        #pragma unroll
        for (int j = 0; j < 2; j++) {
            const float4* src = &d_k4[(b*16 + cq + j)*HWX];
            for (int i = t; i < HR*HC; i += K2_NT) {
                int rr = i / HC, cc = i - rr*HC;
                int r = r_off + rr, col = c_off + cc;
                float4 v = make_float4(0.f, 0.f, 0.f, 0.f);
                if (r >= 0 && r < HH && col >= 0 && col < WW)
                    v = src[r*WW + col];
                ksh[j][i] = v;
            }
            qsh[j][t] = d_q4[(b*16 + cq + j)*HWX + qpix];
        }
        __syncthreads();

        #pragma unroll
        for (int j = 0; j < 2; j++) {
            float4 q4 = qsh[j][t];
            #pragma unroll
            for (int i = 0; i < KK; i++) {
                const float4* kr = &ksh[j][(ri0+i)*HC + ci0];
                #pragma unroll
                for (int jj = 0; jj < KK; jj++) {
                    float4 k4 = kr[jj];
                    attn[i*KK+jj] += q4.x*k4.x + q4.y*k4.y + q4.z*k4.z + q4.w*k4.w;
                }
            }
        }
    }

    // bias + softmax
    const int pbr = 6 - (h - rs);
    const int pbc = 6 - (w - cs);
    float mx = -1e30f;
    #pragma unroll
    for (int i = 0; i < KK; i++) {
        #pragma unroll
        for (int j = 0; j < KK; j++) {
            float a = attn[i*KK+j] + rpbsh[(pbr+i)*13 + pbc + j];
            attn[i*KK+j] = a;
            mx = fmaxf(mx, a);
        }
    }
    float ssum = 0.f;
    #pragma unroll
    for (int i = 0; i < 49; i++) {
        float e = __expf(attn[i] - mx);
        attn[i] = e;
        ssum += e;
    }
    const float inv = 1.f / ssum;

    float cdo = 0.f, mo = 0.f;
    #pragma unroll
    for (int i = 0; i < KK; i++) {
        #pragma unroll
        for (int j = 0; j < KK; j++) {
            float a = attn[i*KK+j];
            cdo += a * cdsh[(ri0+i)*HC + ci0 + j];
            mo  += a * msh[(ri0+i)*HC + ci0 + j];
        }
    }
    cdo *= inv; mo *= inv;

    const int p = b*HWX + h*WW + w;
    const float m = mask[p], cdv = cd[p], sdv = sd[p];
    cdo = cdo*m + cdv*(1.f - m);
    if (sdv > 0.f) { cdo = sdv; mo = m; }
    out[p] = cdo;
    out[BB*HWX + p] = mo;
}

// ---------------------------------------------------------------------------
extern "C" void kernel_launch(void* const* d_in, const int* in_sizes, int n_in,
                              void* d_out, int out_size)
{
    const float* g     = (const float*)d_in[0];
    const float* cd    = (const float*)d_in[1];
    const float* sd    = (const float*)d_in[2];
    const float* mask  = (const float*)d_in[3];
    const float* lnw   = (const float*)d_in[4];
    const float* lnb   = (const float*)d_in[5];
    const float* convw = (const float*)d_in[6];
    const float* convb = (const float*)d_in[7];
    const float* rpb   = (const float*)d_in[8];
    float* out = (float*)d_out;

    mspn_k0<<<(65*128 + 255)/256, 256>>>(convw);

    cudaFuncSetAttribute(mspn_k1, cudaFuncAttributeMaxDynamicSharedMemorySize, K1_SMEM);
    mspn_k1<<<(BB*HWX)/K1_PIX, K1_NT, K1_SMEM>>>(g, cd, mask, lnw, lnb, convb);

    dim3 grid2(WW/TX, HH/TY, BB);
    mspn_k2<<<grid2, K2_NT>>>(cd, sd, mask, rpb, out);
}

// round 8
// speedup vs baseline: 1.8942x; 1.1416x over previous
#include <cuda_runtime.h>
#include <cuda_fp16.h>

#define BB 2
#define CC 64
#define HH 192
#define WW 192
#define HWX (HH*WW)
#define KK 7

// q scratch fp32 quad layout; k scratch fp16 quad layout (half4 per uint2)
__device__ float4 d_q4[BB*16*HWX];
__device__ uint2  d_kh[BB*16*HWX];
// pre-transposed conv weights: wT[c][oc], c in [0,65), oc in [0,128)
__device__ float d_wT[65*128];

__device__ __forceinline__ void ffma2(unsigned long long &acc,
                                      unsigned long long a,
                                      unsigned long long b) {
    asm("fma.rn.f32x2 %0, %1, %2, %0;" : "+l"(acc) : "l"(a), "l"(b));
}
__device__ __forceinline__ float f2lo(unsigned long long v) {
    return __uint_as_float((unsigned)(v & 0xffffffffu));
}
__device__ __forceinline__ float f2hi(unsigned long long v) {
    return __uint_as_float((unsigned)(v >> 32));
}

// ---------------------------------------------------------------------------
// Kernel 0: one-off weight transpose [128][65] -> [65][128].
// ---------------------------------------------------------------------------
__global__ void mspn_k0(const float* __restrict__ convw)
{
    int t = blockIdx.x * 256 + threadIdx.x;
    if (t < 65*128) {
        int oc = t / 65, c = t - oc*65;   // coalesced read of convw[t]
        d_wT[c*128 + oc] = convw[t];
    }
}

// ---------------------------------------------------------------------------
// Kernel 1: LN + [128x65] matvec, register-blocked, f32x2 FMA.
// Weight staging: LDG.128 + STS.128 over consecutive float4 (conflict-free).
// q written fp32 float4; k written fp16 half4.
// ---------------------------------------------------------------------------
#define K1_PIX 64
#define K1_NT 256
#define WSTRIDE 132
#define K1_SMEM (65*K1_PIX*8 + 65*WSTRIDE*4)

__global__ void __launch_bounds__(K1_NT)
mspn_k1(const float* __restrict__ g, const float* __restrict__ cd,
        const float* __restrict__ mask, const float* __restrict__ lnw,
        const float* __restrict__ lnb, const float* __restrict__ convb)
{
    extern __shared__ __align__(16) char dsm[];
    float2* zsh = (float2*)dsm;                       // [65][64]
    float*  wsh = (float*)(dsm + 65*K1_PIX*8);        // [65][WSTRIDE]
    __shared__ float mu_sh[K1_PIX], ri_sh[K1_PIX], mk_sh[K1_PIX];
    __shared__ float bsh[128];

    const int t = threadIdx.x;
    const int p0 = blockIdx.x * K1_PIX;
    const int b = p0 / HWX;
    const int hw0 = p0 - b*HWX;

    // stage weights as float4: both LDG and STS conflict-free
    for (int i = t; i < 65*32; i += K1_NT) {
        int c = i >> 5, ocq = i & 31;
        float4 w4 = ((const float4*)d_wT)[c*32 + ocq];
        *((float4*)(wsh + c*WSTRIDE) + ocq) = w4;
    }
    for (int i = t; i < 64*K1_PIX; i += K1_NT) {
        int c = i >> 6, px = i & 63;
        zsh[c*K1_PIX + px].x = g[(b*CC + c)*HWX + hw0 + px];
    }
    if (t < K1_PIX) {
        float cv = cd[p0 + t];
        zsh[64*K1_PIX + t] = make_float2(cv, cv);
        mk_sh[t] = mask[p0 + t];
    }
    if (t >= 128 && t < 256) bsh[t-128] = convb[t-128];
    __syncthreads();

    if (t < K1_PIX) {
        float s = 0.f;
        #pragma unroll
        for (int c = 0; c < 64; c++) s += zsh[c*K1_PIX + t].x;
        float mu = s * (1.f/64.f);
        float v = 0.f;
        #pragma unroll
        for (int c = 0; c < 64; c++) { float d = zsh[c*K1_PIX + t].x - mu; v += d*d; }
        mu_sh[t] = mu;
        ri_sh[t] = rsqrtf(v * (1.f/64.f) + 1e-6f);
    }
    __syncthreads();

    for (int i = t; i < 64*K1_PIX; i += K1_NT) {
        int c = i >> 6, px = i & 63;
        float v = (zsh[c*K1_PIX + px].x - mu_sh[px]) * ri_sh[px] * lnw[c] + lnb[c];
        zsh[c*K1_PIX + px] = make_float2(v, v);
    }
    __syncthreads();

    const int lane = t & 31, wid = t >> 5;
    const int oc0 = wid * 16;

    unsigned long long acc[16];
    #pragma unroll
    for (int i = 0; i < 16; i++) acc[i] = 0ULL;

    #pragma unroll 13
    for (int c = 0; c < 65; c++) {
        unsigned long long z0 = *(const unsigned long long*)&zsh[c*K1_PIX + lane];
        unsigned long long z1 = *(const unsigned long long*)&zsh[c*K1_PIX + lane + 32];
        const float* wr = &wsh[c*WSTRIDE + oc0];
        ulonglong2 wa = *(const ulonglong2*)(wr);
        ulonglong2 wb = *(const ulonglong2*)(wr + 4);
        ulonglong2 wc = *(const ulonglong2*)(wr + 8);
        ulonglong2 wd = *(const ulonglong2*)(wr + 12);
        ffma2(acc[0], z0, wa.x); ffma2(acc[1], z0, wa.y);
        ffma2(acc[2], z0, wb.x); ffma2(acc[3], z0, wb.y);
        ffma2(acc[4], z0, wc.x); ffma2(acc[5], z0, wc.y);
        ffma2(acc[6], z0, wd.x); ffma2(acc[7], z0, wd.y);
        ffma2(acc[8],  z1, wa.x); ffma2(acc[9],  z1, wa.y);
        ffma2(acc[10], z1, wb.x); ffma2(acc[11], z1, wb.y);
        ffma2(acc[12], z1, wc.x); ffma2(acc[13], z1, wc.y);
        ffma2(acc[14], z1, wd.x); ffma2(acc[15], z1, wd.y);
    }

    const bool isk = (oc0 >= 64);
    const int cq0 = (isk ? oc0 - 64 : oc0) >> 2;
    float bias[16];
    #pragma unroll
    for (int i = 0; i < 16; i++) bias[i] = bsh[oc0 + i];

    #pragma unroll
    for (int px = 0; px < 2; px++) {
        const int pl = lane + px*32;
        const int pix = hw0 + pl;
        const float m = mk_sh[pl];
        float vals[16];
        #pragma unroll
        for (int j = 0; j < 8; j++) {
            unsigned long long a = acc[px*8 + j];
            vals[2*j]   = f2lo(a) + bias[2*j];
            vals[2*j+1] = f2hi(a) + bias[2*j+1];
        }
        if (isk) {
            #pragma unroll
            for (int q = 0; q < 4; q++) {
                __half2 h01 = __floats2half2_rn(vals[4*q]*m,   vals[4*q+1]*m);
                __half2 h23 = __floats2half2_rn(vals[4*q+2]*m, vals[4*q+3]*m);
                uint2 o;
                o.x = *(unsigned*)&h01;
                o.y = *(unsigned*)&h23;
                d_kh[(b*16 + cq0 + q)*HWX + pix] = o;
            }
        } else {
            #pragma unroll
            for (int q = 0; q < 4; q++) {
                float4 o = make_float4(vals[4*q], vals[4*q+1], vals[4*q+2], vals[4*q+3]);
                d_q4[(b*16 + cq0 + q)*HWX + pix] = o;
            }
        }
    }
}

// ---------------------------------------------------------------------------
// Kernel 2: 7x7 clamped-window attention; k tile in fp16 (half crossbar
// bytes), fp32 q + fp32 accumulation. 4 quads per round, 4 rounds.
// ---------------------------------------------------------------------------
#define TX 32
#define TY 8
#define K2_NT 256
#define HR 14
#define HC 38
#define HSZ (HR*HC)

__global__ void __launch_bounds__(K2_NT)
mspn_k2(const float* __restrict__ cd, const float* __restrict__ sd,
        const float* __restrict__ mask, const float* __restrict__ rpb,
        float* __restrict__ out)
{
    __shared__ uint2 ksh[4][HSZ];      // 4 quads, fp16 half4 each
    __shared__ float cdsh[HSZ];
    __shared__ float msh[HSZ];
    __shared__ float rpbsh[169];

    const int t = threadIdx.x;
    const int b  = blockIdx.z;
    const int h0 = blockIdx.y * TY;
    const int w0 = blockIdx.x * TX;
    const int r_off = h0 - 3, c_off = w0 - 3;

    for (int i = t; i < HSZ; i += K2_NT) {
        int rr = i / HC, cc = i - rr*HC;
        int r = r_off + rr, col = c_off + cc;
        float cv = 0.f, mv = 0.f;
        if (r >= 0 && r < HH && col >= 0 && col < WW) {
            int idx = b*HWX + r*WW + col;
            cv = cd[idx]; mv = mask[idx];
        }
        cdsh[i] = cv; msh[i] = mv;
    }
    if (t < 169) rpbsh[t] = rpb[t];

    const int lw = t & 31, lh = t >> 5;
    const int h = h0 + lh, w = w0 + lw;
    int rs = h - 3; if (rs < 0) rs = 0; if (rs > HH-KK) rs = HH-KK;
    int cs = w - 3; if (cs < 0) cs = 0; if (cs > WW-KK) cs = WW-KK;
    const int ri0 = rs - r_off;
    const int ci0 = cs - c_off;

    float attn[49];
    #pragma unroll
    for (int i = 0; i < 49; i++) attn[i] = 0.f;

    const int qpix = h*WW + w;
    const float4* qb = &d_q4[b*16*HWX + qpix];
    const uint2*  kgl = &d_kh[b*16*HWX];

    for (int rd = 0; rd < 4; rd++) {
        // q for this round's 4 quads (LDG overlaps staging)
        float4 q[4];
        #pragma unroll
        for (int s = 0; s < 4; s++) q[s] = qb[(4*rd + s)*HWX];

        __syncthreads();   // previous round's compute done (also orders cdsh)
        #pragma unroll
        for (int s = 0; s < 4; s++) {
            const uint2* src = kgl + (4*rd + s)*HWX;
            for (int i = t; i < HSZ; i += K2_NT) {
                int rr = i / HC, cc = i - rr*HC;
                int r = r_off + rr, col = c_off + cc;
                uint2 v = make_uint2(0u, 0u);
                if (r >= 0 && r < HH && col >= 0 && col < WW)
                    v = src[r*WW + col];
                ksh[s][i] = v;
            }
        }
        __syncthreads();

        #pragma unroll
        for (int s = 0; s < 4; s++) {
            const float4 qq = q[s];
            const uint2* kb = &ksh[s][ri0*HC + ci0];
            #pragma unroll
            for (int i = 0; i < KK; i++) {
                #pragma unroll
                for (int j = 0; j < KK; j++) {
                    uint2 kk = kb[i*HC + j];
                    float2 f01 = __half22float2(*reinterpret_cast<__half2*>(&kk.x));
                    float2 f23 = __half22float2(*reinterpret_cast<__half2*>(&kk.y));
                    attn[i*KK+j] += qq.x*f01.x + qq.y*f01.y + qq.z*f23.x + qq.w*f23.y;
                }
            }
        }
    }

    // bias + softmax
    const int pbr = 6 - (h - rs);
    const int pbc = 6 - (w - cs);
    float mx = -1e30f;
    #pragma unroll
    for (int i = 0; i < KK; i++) {
        #pragma unroll
        for (int j = 0; j < KK; j++) {
            float a = attn[i*KK+j] + rpbsh[(pbr+i)*13 + pbc + j];
            attn[i*KK+j] = a;
            mx = fmaxf(mx, a);
        }
    }
    float ssum = 0.f;
    #pragma unroll
    for (int i = 0; i < 49; i++) {
        float e = __expf(attn[i] - mx);
        attn[i] = e;
        ssum += e;
    }
    const float inv = 1.f / ssum;

    float cdo = 0.f, mo = 0.f;
    #pragma unroll
    for (int i = 0; i < KK; i++) {
        #pragma unroll
        for (int j = 0; j < KK; j++) {
            float a = attn[i*KK+j];
            cdo += a * cdsh[(ri0+i)*HC + ci0 + j];
            mo  += a * msh[(ri0+i)*HC + ci0 + j];
        }
    }
    cdo *= inv; mo *= inv;

    const int p = b*HWX + h*WW + w;
    const float m = mask[p], cdv = cd[p], sdv = sd[p];
    cdo = cdo*m + cdv*(1.f - m);
    if (sdv > 0.f) { cdo = sdv; mo = m; }
    out[p] = cdo;
    out[BB*HWX + p] = mo;
}

// ---------------------------------------------------------------------------
extern "C" void kernel_launch(void* const* d_in, const int* in_sizes, int n_in,
                              void* d_out, int out_size)
{
    const float* g     = (const float*)d_in[0];
    const float* cd    = (const float*)d_in[1];
    const float* sd    = (const float*)d_in[2];
    const float* mask  = (const float*)d_in[3];
    const float* lnw   = (const float*)d_in[4];
    const float* lnb   = (const float*)d_in[5];
    const float* convw = (const float*)d_in[6];
    const float* convb = (const float*)d_in[7];
    const float* rpb   = (const float*)d_in[8];
    float* out = (float*)d_out;

    mspn_k0<<<(65*128 + 255)/256, 256>>>(convw);

    cudaFuncSetAttribute(mspn_k1, cudaFuncAttributeMaxDynamicSharedMemorySize, K1_SMEM);
    mspn_k1<<<(BB*HWX)/K1_PIX, K1_NT, K1_SMEM>>>(g, cd, mask, lnw, lnb, convb);

    dim3 grid2(WW/TX, HH/TY, BB);
    mspn_k2<<<grid2, K2_NT>>>(cd, sd, mask, rpb, out);
}